// round 14
// baseline (speedup 1.0000x reference)
#include <cuda_runtime.h>
#include <cstdint>

#define BB 128
#define LL 1024
#define TT 9
#define CK 32              // backtrace chunk (time steps)
#define NC 32              // backtrace chunks per batch
#define SCH 32             // pipeline chunk (time steps)
#define NSC 32             // pipeline chunks per batch

#define FWD_BLOCKS 16
#define GEMM_BLOCKS 4096   // 131072 rows / 32
#define BT_BLOCKS 512      // 4096 warps / 8
#define EMIT_BLOCKS 512    // 4 per batch

#define PSTRIDE 261        // partials row stride (words); coprime with 32
#define SMEM_BYTES 69632   // 36KB W + 2 x 16KB A double-buffer (P reuses W+A0)

// device scratch (no allocation allowed; zero-initialized at load)
__device__ float g_emis[BB * LL * TT];
__device__ float g_s[BB * LL * TT];
__device__ int   g_len[BB];
__device__ int   g_last[BB];
__device__ unsigned char g_f[BB * NC * TT];
__device__ unsigned char g_cand[BB * NC * TT * CK];
__device__ int g_flag_e[BB * NSC];   // gemm -> fwd
__device__ int g_flag_s[BB * NSC];   // fwd  -> bt
__device__ int g_cnt_bt[BB];         // bt completion counter (-> 32)
__device__ int g_flag_last[BB];      // fwd final argmax done
__device__ int g_cnt_emit[BB];       // emit arrival counter (reset protocol)

__device__ __forceinline__ int ld_acq(const int* p)
{
    int v;
    asm volatile("ld.acquire.gpu.global.b32 %0, [%1];" : "=r"(v) : "l"(p));
    return v;
}
__device__ __forceinline__ void st_rel(int* p, int v)
{
    asm volatile("st.release.gpu.global.b32 [%0], %1;" :: "l"(p), "r"(v));
}

// combine keeping first (lowest) index on ties
#define CMB(vm, im, va, ia, vb, ib)              \
    do { bool p_ = (va) >= (vb);                 \
         (vm) = p_ ? (va) : (vb);                \
         (im) = p_ ? (ia) : (ib); } while (0)

// issue one 16KB enc chunk (32 rows x 512B) into buffer (ch&1) via cp.async
__device__ __forceinline__ void fill_chunk(uint32_t abase, const float* gbase,
                                           int ch, int tid)
{
    const uint32_t buf = (uint32_t)(ch & 1) * 16384u;
#pragma unroll
    for (int k = 0; k < 4; ++k) {
        int seg = tid + k * 256;          // 0..1023
        int rr = seg >> 5;                // row 0..31
        int cc = seg & 31;                // float4 col 0..31
        uint32_t dst = abase + buf + (uint32_t)(rr * 512 + cc * 16);
        const float* src = gbase + (size_t)rr * 1024 + ch * 128 + cc * 4;
        asm volatile("cp.async.cg.shared.global [%0], [%1], 16;"
                     :: "r"(dst), "l"(src));
    }
    asm volatile("cp.async.commit_group;" ::: "memory");
}

// ---------------------------------------------------------------------------
// role: GEMM. cp.async-staged mainloop (math identical to R5/R10/R12:
// kk = ch*32+lane, same fmaf chains) + smem transpose-reduce epilogue (R13).
// block g: chunk c = g>>7 (time steps c*32..), batch b = g&127.
// ---------------------------------------------------------------------------
__device__ void gemm_role(int g, const float* __restrict__ enc,
                          const float* __restrict__ W,
                          const float* __restrict__ bias,
                          unsigned char* sraw)
{
    float4* Wsh = (float4*)sraw;                  // 9*1024 floats = 36KB
    float*  Ash = (float*)(sraw + 36864);         // 2 x 4096 floats = 32KB
    float*  P   = (float*)sraw;                   // reused after mainloop
    const int tid = threadIdx.x;
    for (int i = tid; i < TT * 256; i += 256)
        Wsh[i] = reinterpret_cast<const float4*>(W)[i];

    const int c = g >> 7;
    const int b = g & 127;
    const int warp = tid >> 5;
    const int lane = tid & 31;
    const int rowB = b * LL + c * SCH;            // block's first row
    const float* gbase = enc + (size_t)rowB * 1024;
    const uint32_t abase = (uint32_t)__cvta_generic_to_shared(Ash);

    fill_chunk(abase, gbase, 0, tid);
    fill_chunk(abase, gbase, 1, tid);

    float acc0[TT], acc1[TT], acc2[TT], acc3[TT];
#pragma unroll
    for (int j = 0; j < TT; ++j) { acc0[j] = 0.f; acc1[j] = 0.f; acc2[j] = 0.f; acc3[j] = 0.f; }

    const int r0 = warp * 4;                      // block-relative rows

#pragma unroll
    for (int ch = 0; ch < 8; ++ch) {
        if (ch == 7) asm volatile("cp.async.wait_group 0;" ::: "memory");
        else         asm volatile("cp.async.wait_group 1;" ::: "memory");
        __syncthreads();

        const float4* abuf = reinterpret_cast<const float4*>(Ash) + (ch & 1) * 1024;
        float4 a0 = abuf[(r0 + 0) * 32 + lane];
        float4 a1 = abuf[(r0 + 1) * 32 + lane];
        float4 a2 = abuf[(r0 + 2) * 32 + lane];
        float4 a3 = abuf[(r0 + 3) * 32 + lane];
        const int kk = ch * 32 + lane;
#pragma unroll
        for (int j = 0; j < TT; ++j) {
            float4 w = Wsh[j * 256 + kk];
            acc0[j] = fmaf(a0.x, w.x, fmaf(a0.y, w.y, fmaf(a0.z, w.z, fmaf(a0.w, w.w, acc0[j]))));
            acc1[j] = fmaf(a1.x, w.x, fmaf(a1.y, w.y, fmaf(a1.z, w.z, fmaf(a1.w, w.w, acc1[j]))));
            acc2[j] = fmaf(a2.x, w.x, fmaf(a2.y, w.y, fmaf(a2.z, w.z, fmaf(a2.w, w.w, acc2[j]))));
            acc3[j] = fmaf(a3.x, w.x, fmaf(a3.y, w.y, fmaf(a3.z, w.z, fmaf(a3.w, w.w, acc3[j]))));
        }

        __syncthreads();                           // all reads of buf done
        if (ch < 6) fill_chunk(abase, gbase, ch + 2, tid);
    }

    __syncthreads();                 // mainloop done; smem reusable as P

    // store partials transposed: P[idx][tid], idx = r*9+j
#pragma unroll
    for (int j = 0; j < TT; ++j) {
        P[(0 * TT + j) * PSTRIDE + tid] = acc0[j];
        P[(1 * TT + j) * PSTRIDE + tid] = acc1[j];
        P[(2 * TT + j) * PSTRIDE + tid] = acc2[j];
        P[(3 * TT + j) * PSTRIDE + tid] = acc3[j];
    }
    __syncthreads();

    // reduce: output o = row_local*9 + j; sum 32 lanes of gemm-warp row_local>>2
    for (int o = tid; o < 32 * TT; o += 256) {
        const int row_local = o / TT;
        const int j = o - row_local * TT;
        const int gw = row_local >> 2;
        const int r = row_local & 3;
        const float* p = P + (r * TT + j) * PSTRIDE + gw * 32;
        float v[32];
#pragma unroll
        for (int l = 0; l < 32; ++l) v[l] = p[l];
#pragma unroll
        for (int st = 1; st < 32; st <<= 1)
#pragma unroll
            for (int i = 0; i < 32; i += 2 * st) v[i] += v[i + st];
        g_emis[(size_t)(rowB + row_local) * TT + j] = v[0] + __ldg(&bias[j]);
    }

    __threadfence();
    __syncthreads();
    if (tid == 0) st_rel(&g_flag_e[b * NSC + c], 1);
}

// ---------------------------------------------------------------------------
// role: Viterbi forward (exact sequential). 8 warps/block, warp = batch.
// ---------------------------------------------------------------------------
__device__ void fwd_role(int blk, const void* __restrict__ mask_p,
                         const float* __restrict__ startT,
                         const float* __restrict__ endT,
                         const float* __restrict__ trans,
                         float* __restrict__ out, int out_size)
{
    const int w = threadIdx.x >> 5;
    const int lane = threadIdx.x & 31;
    const int b = blk * 8 + w;
    const bool act = lane < TT;
    const float NEG = __int_as_float(0xff800000);

    // sequence length (mask prefix-true; dtype detected at runtime)
    int cnt = 0;
    const int m0 = ((const int*)mask_p)[0];
    if (m0 == 1) {
        const int* mi = (const int*)mask_p + b * LL;
        for (int t = lane; t < LL; t += 32) cnt += (mi[t] != 0);
    } else if (m0 == 0x3F800000) {
        const float* mf = (const float*)mask_p + b * LL;
        for (int t = lane; t < LL; t += 32) cnt += (mf[t] != 0.f);
    } else {
        const unsigned char* mb = (const unsigned char*)mask_p + b * LL;
        for (int t = lane; t < LL; t += 32) cnt += (mb[t] ? 1 : 0);
    }
#pragma unroll
    for (int off = 16; off; off >>= 1) cnt += __shfl_xor_sync(0xffffffffu, cnt, off);
    const int len = cnt;
    if (lane == 0) g_len[b] = len;

    float tr0 = 0.f, tr1 = 0.f, tr2 = 0.f, tr3 = 0.f, tr4 = 0.f,
          tr5 = 0.f, tr6 = 0.f, tr7 = 0.f, tr8 = 0.f;
    if (act) {
        tr0 = trans[0 * TT + lane]; tr1 = trans[1 * TT + lane]; tr2 = trans[2 * TT + lane];
        tr3 = trans[3 * TT + lane]; tr4 = trans[4 * TT + lane]; tr5 = trans[5 * TT + lane];
        tr6 = trans[6 * TT + lane]; tr7 = trans[7 * TT + lane]; tr8 = trans[8 * TT + lane];
    }

    const int laneC = act ? lane : 0;
    const float* eb = g_emis + (size_t)b * LL * TT + laneC;
    float*       ps = g_s    + (size_t)b * LL * TT + laneC;

    float s = NEG;

#define FSTEP(EV, TI)                                                         \
    do {                                                                      \
        float v0 = __shfl_sync(0xffffffffu, s, 0) + tr0;                      \
        float v1 = __shfl_sync(0xffffffffu, s, 1) + tr1;                      \
        float v2 = __shfl_sync(0xffffffffu, s, 2) + tr2;                      \
        float v3 = __shfl_sync(0xffffffffu, s, 3) + tr3;                      \
        float v4 = __shfl_sync(0xffffffffu, s, 4) + tr4;                      \
        float v5 = __shfl_sync(0xffffffffu, s, 5) + tr5;                      \
        float v6 = __shfl_sync(0xffffffffu, s, 6) + tr6;                      \
        float v7 = __shfl_sync(0xffffffffu, s, 7) + tr7;                      \
        float v8 = __shfl_sync(0xffffffffu, s, 8) + tr8;                      \
        float m01 = fmaxf(v0, v1), m23 = fmaxf(v2, v3);                       \
        float m45 = fmaxf(v4, v5), m67 = fmaxf(v6, v7);                       \
        float m03 = fmaxf(m01, m23), m47 = fmaxf(m45, m67);                   \
        float mA  = fmaxf(fmaxf(m03, m47), v8);                               \
        s = mA + (EV);                                                        \
        if (act) ps[(size_t)(TI) * TT] = s;                                   \
    } while (0)

    int t = 1;
    const int lastC = (len - 1) >> 5;
    float eA[8], eB[8];

    for (int c = 0; c <= lastC; ++c) {
        while (ld_acq(&g_flag_e[b * NSC + c]) == 0) __nanosleep(128);

        if (c == 0) {
            s = act ? (startT[lane] + eb[0]) : NEG;
            if (act) ps[0] = s;
        }
        int cend = (c + 1) * SCH; if (cend > len) cend = len;
        const int cl = (c + 1) * SCH - 1;

#pragma unroll
        for (int u = 0; u < 8; ++u) {
            int tl = t + u; if (tl > cl) tl = cl;
            eA[u] = eb[(size_t)tl * TT];
        }
        while (t + 8 <= cend) {
#pragma unroll
            for (int u = 0; u < 8; ++u) {
                int tl = t + 8 + u; if (tl > cl) tl = cl;
                eB[u] = eb[(size_t)tl * TT];
            }
#pragma unroll
            for (int u = 0; u < 8; ++u) FSTEP(eA[u], t + u);
#pragma unroll
            for (int u = 0; u < 8; ++u) eA[u] = eB[u];
            t += 8;
        }
#pragma unroll
        for (int u = 0; u < 8; ++u)
            if (t + u < cend) FSTEP(eA[u], t + u);
        t = cend;

        __threadfence();
        __syncwarp();
        if (lane == 0) st_rel(&g_flag_s[b * NSC + c], 1);
    }
    if (lane == 0)
        for (int c = lastC + 1; c < NSC; ++c) st_rel(&g_flag_s[b * NSC + c], 1);

    // final argmax (first-index ties)
    float fin = act ? (s + endT[lane]) : NEG;
    float v0 = __shfl_sync(0xffffffffu, fin, 0);
    float v1 = __shfl_sync(0xffffffffu, fin, 1);
    float v2 = __shfl_sync(0xffffffffu, fin, 2);
    float v3 = __shfl_sync(0xffffffffu, fin, 3);
    float v4 = __shfl_sync(0xffffffffu, fin, 4);
    float v5 = __shfl_sync(0xffffffffu, fin, 5);
    float v6 = __shfl_sync(0xffffffffu, fin, 6);
    float v7 = __shfl_sync(0xffffffffu, fin, 7);
    float v8 = __shfl_sync(0xffffffffu, fin, 8);
    float m01, m23, m45, m67, m03, m47, m07, best;
    int   a01, a23, a45, a67, a03, a47, a07, lastTag;
    CMB(m01, a01, v0, 0, v1, 1);  CMB(m23, a23, v2, 2, v3, 3);
    CMB(m45, a45, v4, 4, v5, 5);  CMB(m67, a67, v6, 6, v7, 7);
    CMB(m03, a03, m01, a01, m23, a23);
    CMB(m47, a47, m45, a45, m67, a67);
    CMB(m07, a07, m03, a03, m47, a47);
    CMB(best, lastTag, m07, a07, v8, 8);

    if (lane == 0) {
        g_last[b] = lastTag;
        if (out_size >= BB * LL + BB) out[BB * LL + b] = best;
        __threadfence();
        st_rel(&g_flag_last[b], 1);
    }
}

// ---------------------------------------------------------------------------
// role: per-chunk backtrace. 8 warps/block, warp = (batch, 32-step chunk).
// ---------------------------------------------------------------------------
__device__ void bt_role(int q, const float* __restrict__ trans, unsigned char* sraw)
{
    float* tr_s = (float*)sraw;                               // 81 floats
    float* spA  = tr_s + 88;                                  // 8 * 288 floats
    unsigned char* candA = (unsigned char*)(spA + 8 * 288);   // 8 * 288 bytes

    const int tid = threadIdx.x;
    if (tid < 81) tr_s[tid] = trans[tid];
    __syncthreads();

    const int w = tid >> 5, lane = tid & 31;
    const int wb = q * 8 + w;             // 0..4095
    const int b = wb >> 5;
    const int c32 = wb & 31;
    float* sp = spA + w * 288;
    unsigned char* cand = candA + w * 288;

    while (ld_acq(&g_flag_s[b * NSC + c32]) == 0) __nanosleep(128);

    const int len = g_len[b];
    const int t0 = 1 + c32 * CK;
    const int csize = (t0 + CK <= LL) ? CK : (LL - t0);
    int nsteps = len - t0;
    if (nsteps > csize) nsteps = csize;
    if (nsteps < 0) nsteps = 0;

    const float* src = g_s + ((size_t)b * LL + (t0 - 1)) * TT;
    for (int i = lane; i < nsteps * TT; i += 32) sp[i] = src[i];
    __syncwarp();

    int cur = lane;
    if (lane < TT) {
        for (int u = nsteps - 1; u >= 0; --u) {
            cand[lane * CK + u] = (unsigned char)cur;
            const float* r = &sp[u * TT];
            const float* tc = &tr_s[cur];
            float v0 = r[0] + tc[0 * TT], v1 = r[1] + tc[1 * TT], v2 = r[2] + tc[2 * TT];
            float v3 = r[3] + tc[3 * TT], v4 = r[4] + tc[4 * TT], v5 = r[5] + tc[5 * TT];
            float v6 = r[6] + tc[6 * TT], v7 = r[7] + tc[7 * TT], v8 = r[8] + tc[8 * TT];
            float m01, m23, m45, m67, m03, m47, m07, mA;
            int   a01, a23, a45, a67, a03, a47, a07, aA;
            CMB(m01, a01, v0, 0, v1, 1);  CMB(m23, a23, v2, 2, v3, 3);
            CMB(m45, a45, v4, 4, v5, 5);  CMB(m67, a67, v6, 6, v7, 7);
            CMB(m03, a03, m01, a01, m23, a23);
            CMB(m47, a47, m45, a45, m67, a67);
            CMB(m07, a07, m03, a03, m47, a47);
            CMB(mA,  aA,  m07, a07, v8, 8);
            (void)mA;
            cur = aA;
        }
        g_f[wb * TT + lane] = (unsigned char)cur;
    }
    __syncwarp();

    if (nsteps > 0) {
        unsigned int* dst = (unsigned int*)(g_cand + (size_t)wb * (TT * CK));
        const unsigned int* s4 = (const unsigned int*)cand;
        for (int i = lane; i < (TT * CK) / 4; i += 32) dst[i] = s4[i];
    }
    __syncwarp();
    __threadfence();
    if (lane == 0) atomicAdd(&g_cnt_bt[b], 1);
}

// ---------------------------------------------------------------------------
// role: emit. 4 blocks per batch; composes chunk maps and writes its quarter.
// Last-arriving block of each batch resets that batch's flags.
// ---------------------------------------------------------------------------
__device__ void emit_role(int e, float* __restrict__ out, unsigned char* sraw)
{
    unsigned char* f_s    = sraw;            // NC*TT = 288
    unsigned char* exit_s = sraw + 320;      // NC
    int* misc = (int*)(sraw + 384);          // [0]=tag0, [1]=last-arrival flag

    const int b = e >> 2;
    const int q = e & 3;
    const int tid = threadIdx.x;

    if (tid == 0) {
        while (ld_acq(&g_cnt_bt[b]) < NC) __nanosleep(256);
        while (ld_acq(&g_flag_last[b]) == 0) __nanosleep(256);
        int old = atomicAdd(&g_cnt_emit[b], 1);
        misc[1] = (old == 3);
    }
    __syncthreads();

    if (tid < (NC * TT) / 4)
        ((unsigned int*)f_s)[tid] = ((const unsigned int*)(g_f + b * NC * TT))[tid];
    __syncthreads();

    if (tid == 0) {
        int cur = g_last[b];
        for (int c = NC - 1; c >= 0; --c) {
            exit_s[c] = (unsigned char)cur;
            cur = f_s[c * TT + cur];
        }
        misc[0] = cur;
    }
    __syncthreads();

    const int len = g_len[b];
    const int t = q * 256 + tid;          // 256 threads, one element each
    float v;
    if (t == 0) {
        v = (float)misc[0];
    } else if (t < len) {
        int c = (t - 1) >> 5;
        int u = (t - 1) & 31;
        v = (float)g_cand[(((size_t)b * NC + c) * TT + exit_s[c]) * CK + u];
    } else {
        v = 0.f;
    }
    out[(size_t)b * LL + t] = v;

    if (misc[1]) {
        if (tid < NSC) {
            g_flag_e[b * NSC + tid] = 0;
            g_flag_s[b * NSC + tid] = 0;
        }
        if (tid == 0) {
            g_cnt_bt[b] = 0;
            g_flag_last[b] = 0;
            g_cnt_emit[b] = 0;
        }
    }
}

// ---------------------------------------------------------------------------
// fused kernel (single launch, dynamic smem 68KB, 3 blocks/SM)
// ---------------------------------------------------------------------------
__global__ void __launch_bounds__(256, 3) fused_k(const float* __restrict__ enc,
                                                  const void* __restrict__ mask_p,
                                                  const float* __restrict__ W,
                                                  const float* __restrict__ bias,
                                                  const float* __restrict__ startT,
                                                  const float* __restrict__ endT,
                                                  const float* __restrict__ trans,
                                                  float* __restrict__ out, int out_size)
{
    extern __shared__ __align__(16) unsigned char sraw[];
    const int bi = blockIdx.x;
    if (bi < FWD_BLOCKS) {
        fwd_role(bi, mask_p, startT, endT, trans, out, out_size);
    } else if (bi < FWD_BLOCKS + GEMM_BLOCKS) {
        gemm_role(bi - FWD_BLOCKS, enc, W, bias, sraw);
    } else if (bi < FWD_BLOCKS + GEMM_BLOCKS + BT_BLOCKS) {
        bt_role(bi - FWD_BLOCKS - GEMM_BLOCKS, trans, sraw);
    } else {
        emit_role(bi - FWD_BLOCKS - GEMM_BLOCKS - BT_BLOCKS, out, sraw);
    }
}

// ---------------------------------------------------------------------------
extern "C" void kernel_launch(void* const* d_in, const int* in_sizes, int n_in,
                              void* d_out, int out_size)
{
    const float* enc    = (const float*)d_in[0];
    const void*  mask   = d_in[1];
    const float* W      = (const float*)d_in[2];
    const float* bias   = (const float*)d_in[3];
    const float* startT = (const float*)d_in[4];
    const float* endT   = (const float*)d_in[5];
    const float* trans  = (const float*)d_in[6];
    float* out = (float*)d_out;

    cudaFuncSetAttribute(fused_k, cudaFuncAttributeMaxDynamicSharedMemorySize,
                         SMEM_BYTES);

    fused_k<<<FWD_BLOCKS + GEMM_BLOCKS + BT_BLOCKS + EMIT_BLOCKS, 256, SMEM_BYTES>>>(
        enc, mask, W, bias, startT, endT, trans, out, out_size);
}

// round 15
// speedup vs baseline: 1.1120x; 1.1120x over previous
#include <cuda_runtime.h>
#include <cstdint>

#define BB 128
#define LL 1024
#define TT 9
#define CK 32              // backtrace chunk (time steps)
#define NC 32              // backtrace chunks per batch
#define SCH 32             // pipeline chunk (time steps)
#define NSC 32             // pipeline chunks per batch

#define FWD_BLOCKS 16
#define GEMM_BLOCKS 4096   // 131072 rows / 32
#define BT_BLOCKS 512      // 4096 warps / 8
#define EMIT_BLOCKS 512    // 4 per batch

#define PSTRIDE 261        // partials row stride (words); coprime with 32

// device scratch (no allocation allowed; zero-initialized at load)
__device__ float g_emis[BB * LL * TT];
__device__ float g_s[BB * LL * TT];
__device__ int   g_len[BB];
__device__ int   g_last[BB];
__device__ unsigned char g_f[BB * NC * TT];
__device__ unsigned char g_cand[BB * NC * TT * CK];
__device__ int g_flag_e[BB * NSC];   // gemm -> fwd
__device__ int g_flag_s[BB * NSC];   // fwd  -> bt
__device__ int g_cnt_bt[BB];         // bt completion counter (-> 32)
__device__ int g_flag_last[BB];      // fwd final argmax done
__device__ int g_cnt_emit[BB];       // emit arrival counter (reset protocol)

__device__ __forceinline__ int ld_acq(const int* p)
{
    int v;
    asm volatile("ld.acquire.gpu.global.b32 %0, [%1];" : "=r"(v) : "l"(p));
    return v;
}
__device__ __forceinline__ void st_rel(int* p, int v)
{
    asm volatile("st.release.gpu.global.b32 [%0], %1;" :: "l"(p), "r"(v));
}

// combine keeping first (lowest) index on ties
#define CMB(vm, im, va, ia, vb, ib)              \
    do { bool p_ = (va) >= (vb);                 \
         (vm) = p_ ? (va) : (vb);                \
         (im) = p_ ? (ia) : (ib); } while (0)

// ---------------------------------------------------------------------------
// role: GEMM. R13 layout (8 warps x 4 rows, 32-lane K-split) with an explicit
// 2-stage register pipeline: iteration it+1's a-loads issue before it's FFMAs.
// Epilogue: smem transpose-reduce (R13). Math order identical to R13.
// block g: chunk c = g>>7 (time steps c*32..), batch b = g&127.
// ---------------------------------------------------------------------------
__device__ void gemm_role(int g, const float* __restrict__ enc,
                          const float* __restrict__ W,
                          const float* __restrict__ bias,
                          unsigned char* sraw)
{
    float4* Wsh = (float4*)sraw;                 // 9*1024 floats = 36KB
    float*  P   = (float*)sraw;                  // reused after mainloop
    const int tid = threadIdx.x;
    for (int i = tid; i < TT * 256; i += 256)
        Wsh[i] = reinterpret_cast<const float4*>(W)[i];

    __syncthreads();

    const int c = g >> 7;
    const int b = g & 127;
    const int warp = tid >> 5;
    const int lane = tid & 31;
    const int rowB = b * LL + c * SCH;
    const int row0 = rowB + warp * 4;
    const float4* e0 = reinterpret_cast<const float4*>(enc) + (size_t)row0 * 256;

    float acc0[TT], acc1[TT], acc2[TT], acc3[TT];
#pragma unroll
    for (int j = 0; j < TT; ++j) { acc0[j] = 0.f; acc1[j] = 0.f; acc2[j] = 0.f; acc3[j] = 0.f; }

    // explicit 2-stage pipeline: prefetch it+1 before computing it
    float4 pa0 = e0[0 * 256 + lane];
    float4 pa1 = e0[1 * 256 + lane];
    float4 pa2 = e0[2 * 256 + lane];
    float4 pa3 = e0[3 * 256 + lane];

#pragma unroll
    for (int it = 0; it < 8; ++it) {
        float4 a0 = pa0, a1 = pa1, a2 = pa2, a3 = pa3;
        if (it < 7) {
            const int kn = (it + 1) * 32 + lane;
            pa0 = e0[0 * 256 + kn];
            pa1 = e0[1 * 256 + kn];
            pa2 = e0[2 * 256 + kn];
            pa3 = e0[3 * 256 + kn];
        }
        const int kk = it * 32 + lane;
#pragma unroll
        for (int j = 0; j < TT; ++j) {
            float4 w = Wsh[j * 256 + kk];
            acc0[j] = fmaf(a0.x, w.x, fmaf(a0.y, w.y, fmaf(a0.z, w.z, fmaf(a0.w, w.w, acc0[j]))));
            acc1[j] = fmaf(a1.x, w.x, fmaf(a1.y, w.y, fmaf(a1.z, w.z, fmaf(a1.w, w.w, acc1[j]))));
            acc2[j] = fmaf(a2.x, w.x, fmaf(a2.y, w.y, fmaf(a2.z, w.z, fmaf(a2.w, w.w, acc2[j]))));
            acc3[j] = fmaf(a3.x, w.x, fmaf(a3.y, w.y, fmaf(a3.z, w.z, fmaf(a3.w, w.w, acc3[j]))));
        }
    }

    __syncthreads();                 // all warps done reading Wsh

    // store partials transposed: P[idx][tid], idx = r*9+j
#pragma unroll
    for (int j = 0; j < TT; ++j) {
        P[(0 * TT + j) * PSTRIDE + tid] = acc0[j];
        P[(1 * TT + j) * PSTRIDE + tid] = acc1[j];
        P[(2 * TT + j) * PSTRIDE + tid] = acc2[j];
        P[(3 * TT + j) * PSTRIDE + tid] = acc3[j];
    }
    __syncthreads();

    // reduce: output o = row_local*9 + j; sum 32 lanes of gemm-warp row_local>>2
    for (int o = tid; o < 32 * TT; o += 256) {
        const int row_local = o / TT;
        const int j = o - row_local * TT;
        const int gw = row_local >> 2;
        const int r = row_local & 3;
        const float* p = P + (r * TT + j) * PSTRIDE + gw * 32;
        float v[32];
#pragma unroll
        for (int l = 0; l < 32; ++l) v[l] = p[l];
#pragma unroll
        for (int st = 1; st < 32; st <<= 1)
#pragma unroll
            for (int i = 0; i < 32; i += 2 * st) v[i] += v[i + st];
        g_emis[(size_t)(rowB + row_local) * TT + j] = v[0] + __ldg(&bias[j]);
    }

    __threadfence();
    __syncthreads();
    if (tid == 0) st_rel(&g_flag_e[b * NSC + c], 1);
}

// ---------------------------------------------------------------------------
// role: Viterbi forward (exact sequential). 8 warps/block, warp = batch.
// ---------------------------------------------------------------------------
__device__ void fwd_role(int blk, const void* __restrict__ mask_p,
                         const float* __restrict__ startT,
                         const float* __restrict__ endT,
                         const float* __restrict__ trans,
                         float* __restrict__ out, int out_size)
{
    const int w = threadIdx.x >> 5;
    const int lane = threadIdx.x & 31;
    const int b = blk * 8 + w;
    const bool act = lane < TT;
    const float NEG = __int_as_float(0xff800000);

    // sequence length (mask prefix-true; dtype detected at runtime)
    int cnt = 0;
    const int m0 = ((const int*)mask_p)[0];
    if (m0 == 1) {
        const int* mi = (const int*)mask_p + b * LL;
        for (int t = lane; t < LL; t += 32) cnt += (mi[t] != 0);
    } else if (m0 == 0x3F800000) {
        const float* mf = (const float*)mask_p + b * LL;
        for (int t = lane; t < LL; t += 32) cnt += (mf[t] != 0.f);
    } else {
        const unsigned char* mb = (const unsigned char*)mask_p + b * LL;
        for (int t = lane; t < LL; t += 32) cnt += (mb[t] ? 1 : 0);
    }
#pragma unroll
    for (int off = 16; off; off >>= 1) cnt += __shfl_xor_sync(0xffffffffu, cnt, off);
    const int len = cnt;
    if (lane == 0) g_len[b] = len;

    float tr0 = 0.f, tr1 = 0.f, tr2 = 0.f, tr3 = 0.f, tr4 = 0.f,
          tr5 = 0.f, tr6 = 0.f, tr7 = 0.f, tr8 = 0.f;
    if (act) {
        tr0 = trans[0 * TT + lane]; tr1 = trans[1 * TT + lane]; tr2 = trans[2 * TT + lane];
        tr3 = trans[3 * TT + lane]; tr4 = trans[4 * TT + lane]; tr5 = trans[5 * TT + lane];
        tr6 = trans[6 * TT + lane]; tr7 = trans[7 * TT + lane]; tr8 = trans[8 * TT + lane];
    }

    const int laneC = act ? lane : 0;
    const float* eb = g_emis + (size_t)b * LL * TT + laneC;
    float*       ps = g_s    + (size_t)b * LL * TT + laneC;

    float s = NEG;

#define FSTEP(EV, TI)                                                         \
    do {                                                                      \
        float v0 = __shfl_sync(0xffffffffu, s, 0) + tr0;                      \
        float v1 = __shfl_sync(0xffffffffu, s, 1) + tr1;                      \
        float v2 = __shfl_sync(0xffffffffu, s, 2) + tr2;                      \
        float v3 = __shfl_sync(0xffffffffu, s, 3) + tr3;                      \
        float v4 = __shfl_sync(0xffffffffu, s, 4) + tr4;                      \
        float v5 = __shfl_sync(0xffffffffu, s, 5) + tr5;                      \
        float v6 = __shfl_sync(0xffffffffu, s, 6) + tr6;                      \
        float v7 = __shfl_sync(0xffffffffu, s, 7) + tr7;                      \
        float v8 = __shfl_sync(0xffffffffu, s, 8) + tr8;                      \
        float m01 = fmaxf(v0, v1), m23 = fmaxf(v2, v3);                       \
        float m45 = fmaxf(v4, v5), m67 = fmaxf(v6, v7);                       \
        float m03 = fmaxf(m01, m23), m47 = fmaxf(m45, m67);                   \
        float mA  = fmaxf(fmaxf(m03, m47), v8);                               \
        s = mA + (EV);                                                        \
        if (act) ps[(size_t)(TI) * TT] = s;                                   \
    } while (0)

    int t = 1;
    const int lastC = (len - 1) >> 5;
    float eA[8], eB[8];

    for (int c = 0; c <= lastC; ++c) {
        while (ld_acq(&g_flag_e[b * NSC + c]) == 0) __nanosleep(128);

        if (c == 0) {
            s = act ? (startT[lane] + eb[0]) : NEG;
            if (act) ps[0] = s;
        }
        int cend = (c + 1) * SCH; if (cend > len) cend = len;
        const int cl = (c + 1) * SCH - 1;

#pragma unroll
        for (int u = 0; u < 8; ++u) {
            int tl = t + u; if (tl > cl) tl = cl;
            eA[u] = eb[(size_t)tl * TT];
        }
        while (t + 8 <= cend) {
#pragma unroll
            for (int u = 0; u < 8; ++u) {
                int tl = t + 8 + u; if (tl > cl) tl = cl;
                eB[u] = eb[(size_t)tl * TT];
            }
#pragma unroll
            for (int u = 0; u < 8; ++u) FSTEP(eA[u], t + u);
#pragma unroll
            for (int u = 0; u < 8; ++u) eA[u] = eB[u];
            t += 8;
        }
#pragma unroll
        for (int u = 0; u < 8; ++u)
            if (t + u < cend) FSTEP(eA[u], t + u);
        t = cend;

        __threadfence();
        __syncwarp();
        if (lane == 0) st_rel(&g_flag_s[b * NSC + c], 1);
    }
    if (lane == 0)
        for (int c = lastC + 1; c < NSC; ++c) st_rel(&g_flag_s[b * NSC + c], 1);

    // final argmax (first-index ties)
    float fin = act ? (s + endT[lane]) : NEG;
    float v0 = __shfl_sync(0xffffffffu, fin, 0);
    float v1 = __shfl_sync(0xffffffffu, fin, 1);
    float v2 = __shfl_sync(0xffffffffu, fin, 2);
    float v3 = __shfl_sync(0xffffffffu, fin, 3);
    float v4 = __shfl_sync(0xffffffffu, fin, 4);
    float v5 = __shfl_sync(0xffffffffu, fin, 5);
    float v6 = __shfl_sync(0xffffffffu, fin, 6);
    float v7 = __shfl_sync(0xffffffffu, fin, 7);
    float v8 = __shfl_sync(0xffffffffu, fin, 8);
    float m01, m23, m45, m67, m03, m47, m07, best;
    int   a01, a23, a45, a67, a03, a47, a07, lastTag;
    CMB(m01, a01, v0, 0, v1, 1);  CMB(m23, a23, v2, 2, v3, 3);
    CMB(m45, a45, v4, 4, v5, 5);  CMB(m67, a67, v6, 6, v7, 7);
    CMB(m03, a03, m01, a01, m23, a23);
    CMB(m47, a47, m45, a45, m67, a67);
    CMB(m07, a07, m03, a03, m47, a47);
    CMB(best, lastTag, m07, a07, v8, 8);

    if (lane == 0) {
        g_last[b] = lastTag;
        if (out_size >= BB * LL + BB) out[BB * LL + b] = best;
        __threadfence();
        st_rel(&g_flag_last[b], 1);
    }
}

// ---------------------------------------------------------------------------
// role: per-chunk backtrace. 8 warps/block, warp = (batch, 32-step chunk).
// ---------------------------------------------------------------------------
__device__ void bt_role(int q, const float* __restrict__ trans, unsigned char* sraw)
{
    float* tr_s = (float*)sraw;                               // 81 floats
    float* spA  = tr_s + 88;                                  // 8 * 288 floats
    unsigned char* candA = (unsigned char*)(spA + 8 * 288);   // 8 * 288 bytes

    const int tid = threadIdx.x;
    if (tid < 81) tr_s[tid] = trans[tid];
    __syncthreads();

    const int w = tid >> 5, lane = tid & 31;
    const int wb = q * 8 + w;             // 0..4095
    const int b = wb >> 5;
    const int c32 = wb & 31;
    float* sp = spA + w * 288;
    unsigned char* cand = candA + w * 288;

    while (ld_acq(&g_flag_s[b * NSC + c32]) == 0) __nanosleep(128);

    const int len = g_len[b];
    const int t0 = 1 + c32 * CK;
    const int csize = (t0 + CK <= LL) ? CK : (LL - t0);
    int nsteps = len - t0;
    if (nsteps > csize) nsteps = csize;
    if (nsteps < 0) nsteps = 0;

    const float* src = g_s + ((size_t)b * LL + (t0 - 1)) * TT;
    for (int i = lane; i < nsteps * TT; i += 32) sp[i] = src[i];
    __syncwarp();

    int cur = lane;
    if (lane < TT) {
        for (int u = nsteps - 1; u >= 0; --u) {
            cand[lane * CK + u] = (unsigned char)cur;
            const float* r = &sp[u * TT];
            const float* tc = &tr_s[cur];
            float v0 = r[0] + tc[0 * TT], v1 = r[1] + tc[1 * TT], v2 = r[2] + tc[2 * TT];
            float v3 = r[3] + tc[3 * TT], v4 = r[4] + tc[4 * TT], v5 = r[5] + tc[5 * TT];
            float v6 = r[6] + tc[6 * TT], v7 = r[7] + tc[7 * TT], v8 = r[8] + tc[8 * TT];
            float m01, m23, m45, m67, m03, m47, m07, mA;
            int   a01, a23, a45, a67, a03, a47, a07, aA;
            CMB(m01, a01, v0, 0, v1, 1);  CMB(m23, a23, v2, 2, v3, 3);
            CMB(m45, a45, v4, 4, v5, 5);  CMB(m67, a67, v6, 6, v7, 7);
            CMB(m03, a03, m01, a01, m23, a23);
            CMB(m47, a47, m45, a45, m67, a67);
            CMB(m07, a07, m03, a03, m47, a47);
            CMB(mA,  aA,  m07, a07, v8, 8);
            (void)mA;
            cur = aA;
        }
        g_f[wb * TT + lane] = (unsigned char)cur;
    }
    __syncwarp();

    if (nsteps > 0) {
        unsigned int* dst = (unsigned int*)(g_cand + (size_t)wb * (TT * CK));
        const unsigned int* s4 = (const unsigned int*)cand;
        for (int i = lane; i < (TT * CK) / 4; i += 32) dst[i] = s4[i];
    }
    __syncwarp();
    __threadfence();
    if (lane == 0) atomicAdd(&g_cnt_bt[b], 1);
}

// ---------------------------------------------------------------------------
// role: emit. 4 blocks per batch; composes chunk maps and writes its quarter.
// Last-arriving block of each batch resets that batch's flags.
// ---------------------------------------------------------------------------
__device__ void emit_role(int e, float* __restrict__ out, unsigned char* sraw)
{
    unsigned char* f_s    = sraw;            // NC*TT = 288
    unsigned char* exit_s = sraw + 320;      // NC
    int* misc = (int*)(sraw + 384);          // [0]=tag0, [1]=last-arrival flag

    const int b = e >> 2;
    const int q = e & 3;
    const int tid = threadIdx.x;

    if (tid == 0) {
        while (ld_acq(&g_cnt_bt[b]) < NC) __nanosleep(256);
        while (ld_acq(&g_flag_last[b]) == 0) __nanosleep(256);
        int old = atomicAdd(&g_cnt_emit[b], 1);
        misc[1] = (old == 3);
    }
    __syncthreads();

    if (tid < (NC * TT) / 4)
        ((unsigned int*)f_s)[tid] = ((const unsigned int*)(g_f + b * NC * TT))[tid];
    __syncthreads();

    if (tid == 0) {
        int cur = g_last[b];
        for (int c = NC - 1; c >= 0; --c) {
            exit_s[c] = (unsigned char)cur;
            cur = f_s[c * TT + cur];
        }
        misc[0] = cur;
    }
    __syncthreads();

    const int len = g_len[b];
    const int t = q * 256 + tid;          // 256 threads, one element each
    float v;
    if (t == 0) {
        v = (float)misc[0];
    } else if (t < len) {
        int c = (t - 1) >> 5;
        int u = (t - 1) & 31;
        v = (float)g_cand[(((size_t)b * NC + c) * TT + exit_s[c]) * CK + u];
    } else {
        v = 0.f;
    }
    out[(size_t)b * LL + t] = v;

    if (misc[1]) {
        if (tid < NSC) {
            g_flag_e[b * NSC + tid] = 0;
            g_flag_s[b * NSC + tid] = 0;
        }
        if (tid == 0) {
            g_cnt_bt[b] = 0;
            g_flag_last[b] = 0;
            g_cnt_emit[b] = 0;
        }
    }
}

// ---------------------------------------------------------------------------
// fused kernel (single launch). (256,2): allow up to 128 regs for deep
// per-warp load pipelining; 2 blocks/SM.
// ---------------------------------------------------------------------------
__global__ void __launch_bounds__(256, 2) fused_k(const float* __restrict__ enc,
                                                  const void* __restrict__ mask_p,
                                                  const float* __restrict__ W,
                                                  const float* __restrict__ bias,
                                                  const float* __restrict__ startT,
                                                  const float* __restrict__ endT,
                                                  const float* __restrict__ trans,
                                                  float* __restrict__ out, int out_size)
{
    __shared__ __align__(16) unsigned char sraw[37632];   // max(W 36864, P 36*261*4)
    const int bi = blockIdx.x;
    if (bi < FWD_BLOCKS) {
        fwd_role(bi, mask_p, startT, endT, trans, out, out_size);
    } else if (bi < FWD_BLOCKS + GEMM_BLOCKS) {
        gemm_role(bi - FWD_BLOCKS, enc, W, bias, sraw);
    } else if (bi < FWD_BLOCKS + GEMM_BLOCKS + BT_BLOCKS) {
        bt_role(bi - FWD_BLOCKS - GEMM_BLOCKS, trans, sraw);
    } else {
        emit_role(bi - FWD_BLOCKS - GEMM_BLOCKS - BT_BLOCKS, out, sraw);
    }
}

// ---------------------------------------------------------------------------
extern "C" void kernel_launch(void* const* d_in, const int* in_sizes, int n_in,
                              void* d_out, int out_size)
{
    const float* enc    = (const float*)d_in[0];
    const void*  mask   = d_in[1];
    const float* W      = (const float*)d_in[2];
    const float* bias   = (const float*)d_in[3];
    const float* startT = (const float*)d_in[4];
    const float* endT   = (const float*)d_in[5];
    const float* trans  = (const float*)d_in[6];
    float* out = (float*)d_out;

    fused_k<<<FWD_BLOCKS + GEMM_BLOCKS + BT_BLOCKS + EMIT_BLOCKS, 256>>>(
        enc, mask, W, bias, startT, endT, trans, out, out_size);
}